// round 8
// baseline (speedup 1.0000x reference)
#include <cuda_runtime.h>
#include <cstdint>

// out[b,t,c] = sum_s exp(-4*(sw[b,t] + s - t)^2) * input[b,s,c]
// WIDTH=0.25 -> 3-tap window {r-1, r, r+1}, r = round(t - sw); dropped taps
// have wgt <= exp(-9) = 1.23e-4 vs kept sum >= 0.74 -> rel err ~2e-4 worst
// case (threshold 1e-3; measured 4.5e-5).
//
// B=16, S=4096, T=2048, C=128.
// Latency-hiding via cp.async (LDGSTS): each warp owns 4 t (two halves of
// 2 t). All 12 gathered rows are put in flight as register-free
// global->smem copies, pipelined: issue half0 (group), issue half1 (group),
// wait 1 -> compute half0, wait 0 -> compute half1. Each lane reads back
// exactly the 16B it copied, so no syncwarp is needed. No block barrier,
// no over-fetch — fixes round-5's smem failure modes while restoring
// round-3's MLP at round-4's register count.
// smem: 8 warps * 12 rows * 512B = 48KB.

#define S_DIM 4096
#define T_DIM 2048
#define C_DIM 128
#define C4    (C_DIM / 4)

__device__ __forceinline__ void cp_async16(unsigned int smem_dst,
                                           const void* gmem_src) {
    asm volatile("cp.async.cg.shared.global [%0], [%1], 16;\n"
                 :: "r"(smem_dst), "l"(gmem_src));
}
__device__ __forceinline__ void cp_commit() {
    asm volatile("cp.async.commit_group;\n");
}
template <int N>
__device__ __forceinline__ void cp_wait() {
    asm volatile("cp.async.wait_group %0;\n" :: "n"(N));
}

__global__ __launch_bounds__(256)
void shifting_cpasync_kernel(const float* __restrict__ inp,
                             const float* __restrict__ sw,
                             float* __restrict__ out) {
    __shared__ float4 sm[8 * 12 * 32];                 // 48 KB

    const int b    = blockIdx.y;
    const int warp = threadIdx.x >> 5;                 // 0..7
    const int lane = threadIdx.x & 31;
    const int t0   = (blockIdx.x << 5) + (warp << 2);  // 4 t per warp

    const float4* __restrict__ row =
        (const float4*)(inp + (size_t)b * S_DIM * C_DIM);

    // sw[t0..t0+3] in one broadcast float4 (t0 % 4 == 0).
    const float4 swv = *(const float4*)(sw + b * T_DIM + t0);
    const float w[4] = {swv.x, swv.y, swv.z, swv.w};

    int   r[4];
    float f[4];                                        // f = w + r - t
#pragma unroll
    for (int j = 0; j < 4; ++j) {
        r[j] = __float2int_rn((float)(t0 + j) - w[j]);
        f[j] = w[j] + (float)(r[j] - (t0 + j));
    }

    // Warp's smem slice: 12 row slots of 32 float4.
    float4* slice = &sm[warp * 12 * 32];
    const unsigned int slice_base =
        (unsigned int)__cvta_generic_to_shared(slice) +
        (unsigned int)(lane * 16);

    // Issue all 12 row copies: slot = half*6 + jj*3 + (i+1).
#pragma unroll
    for (int half = 0; half < 2; ++half) {
#pragma unroll
        for (int jj = 0; jj < 2; ++jj) {
            const int j = (half << 1) + jj;
#pragma unroll
            for (int i = -1; i <= 1; ++i) {
                const int s    = r[j] + i;
                const int s_ld = (s < 0) ? 0 : s;      // clamp; wgt=0 later
                const int slot = half * 6 + jj * 3 + (i + 1);
                cp_async16(slice_base + (unsigned int)(slot * 512),
                           &row[s_ld * C4 + lane]);
            }
        }
        cp_commit();                                   // group per half
    }

    // Compute halves as their groups land.
#pragma unroll
    for (int half = 0; half < 2; ++half) {
        if (half == 0) cp_wait<1>(); else cp_wait<0>();
#pragma unroll
        for (int jj = 0; jj < 2; ++jj) {
            const int j = (half << 1) + jj;
            float4 acc = make_float4(0.f, 0.f, 0.f, 0.f);
#pragma unroll
            for (int i = -1; i <= 1; ++i) {
                const float d   = f[j] + (float)i;
                float       wgt = __expf(-4.0f * d * d);
                if (r[j] + i < 0) wgt = 0.f;
                const float4 v = slice[(half * 6 + jj * 3 + (i + 1)) * 32 + lane];
                acc.x = fmaf(wgt, v.x, acc.x);
                acc.y = fmaf(wgt, v.y, acc.y);
                acc.z = fmaf(wgt, v.z, acc.z);
                acc.w = fmaf(wgt, v.w, acc.w);
            }
            float4* __restrict__ o =
                (float4*)(out + ((size_t)b * T_DIM + (t0 + j)) * C_DIM);
            o[lane] = acc;
        }
    }
}

extern "C" void kernel_launch(void* const* d_in, const int* in_sizes, int n_in,
                              void* d_out, int out_size) {
    const float* inp = (const float*)d_in[0];   // (B, S, C) fp32
    const float* sw  = (const float*)d_in[1];   // (B, T)   fp32
    float* out       = (float*)d_out;           // (B, T, C) fp32

    dim3 grid(T_DIM / 32, 16, 1);   // (64, 16) = 1024 blocks
    dim3 block(256, 1, 1);
    shifting_cpasync_kernel<<<grid, block>>>(inp, sw, out);
}

// round 9
// speedup vs baseline: 1.5305x; 1.5305x over previous
#include <cuda_runtime.h>
#include <cstdint>

// out[b,t,c] = sum_s exp(-4*(sw[b,t] + s - t)^2) * input[b,s,c]
// WIDTH=0.25 -> 3-tap window {r-1, r, r+1}, r = round(t - sw); dropped taps
// weigh <= exp(-9) = 1.23e-4 vs kept sum >= 0.74 -> worst-case rel err ~3e-4
// (threshold 1e-3; measured 4.5e-5). 2-tap was analyzed and REJECTED: global
// rel err ~4e-3 > threshold.
//
// Round-9: identical structure to the 8.70us round-4 kernel (4 t per warp,
// two halves of 2 t = 6 in-flight LDG.128, 256-thr blocks, grid 1024),
// with issued-instruction count minimized:
//  - taps addressed as one base pointer per t + immediate offsets
//    (+512B, +1024B) instead of per-tap index math
//  - weights via exp2 factorization: -4(f+i)^2*log2e = A -/+ u - D with
//    A = -5.7708 f^2, u = 11.5416 f, D = 5.7708 -> 3 ALU + 3 raw EX2 per t
//  - sw[t0..t0+3] as one broadcast float4

#define S_DIM 4096
#define T_DIM 2048
#define C_DIM 128
#define C4    (C_DIM / 4)

__device__ __forceinline__ float ex2(float x) {
    float y;
    asm("ex2.approx.f32 %0, %1;" : "=f"(y) : "f"(x));
    return y;
}

__global__ __launch_bounds__(256)
void shifting_window_kernel(const float* __restrict__ inp,
                            const float* __restrict__ sw,
                            float* __restrict__ out) {
    const int b    = blockIdx.y;
    const int warp = threadIdx.x >> 5;                 // 0..7
    const int lane = threadIdx.x & 31;
    const int t0   = (blockIdx.x << 5) + (warp << 2);  // 4 t per warp

    const float4* __restrict__ row =
        (const float4*)(inp + (size_t)b * S_DIM * C_DIM);

    // sw[t0..t0+3] in one broadcast float4 (t0 % 4 == 0, 16B aligned).
    const float4 swv = *(const float4*)(sw + b * T_DIM + t0);
    const float wv[4] = {swv.x, swv.y, swv.z, swv.w};

    int   r[4];
    float wm[4], w0[4], wp[4];
#pragma unroll
    for (int j = 0; j < 4; ++j) {
        r[j] = __float2int_rn((float)(t0 + j) - wv[j]);
        const float f = wv[j] + (float)(r[j] - (t0 + j));   // frac in [-0.5,0.5]
        const float A = -5.770780f * f * f;                 // -4 f^2 log2e
        const float u = 11.541560f * f;                     //  8 f   log2e
        w0[j] = ex2(A);
        wm[j] = ex2(A + u - 5.770780f);                     // tap r-1
        wp[j] = ex2(A - u - 5.770780f);                     // tap r+1
    }

    if (t0 >= 8) {
        // Hot path: s in [t-6, t+6] subset of [2, 2054) -> no bounds checks.
#pragma unroll
        for (int half = 0; half < 2; ++half) {
            const int j0 = half << 1;
            float4 acc[2];
#pragma unroll
            for (int jj = 0; jj < 2; ++jj) {
                const int j = j0 + jj;
                // Base pointer at tap r-1; other taps at +C4 / +2*C4
                // (immediate offsets +512B / +1024B in SASS).
                const float4* p = &row[(r[j] - 1) * C4 + lane];
                const float4 vm = p[0];
                const float4 v0 = p[C4];
                const float4 vp = p[2 * C4];
                float4 a;
                a.x = wm[j] * vm.x; a.y = wm[j] * vm.y;
                a.z = wm[j] * vm.z; a.w = wm[j] * vm.w;
                a.x = fmaf(w0[j], v0.x, a.x); a.y = fmaf(w0[j], v0.y, a.y);
                a.z = fmaf(w0[j], v0.z, a.z); a.w = fmaf(w0[j], v0.w, a.w);
                a.x = fmaf(wp[j], vp.x, a.x); a.y = fmaf(wp[j], vp.y, a.y);
                a.z = fmaf(wp[j], vp.z, a.z); a.w = fmaf(wp[j], vp.w, a.w);
                acc[jj] = a;
            }
#pragma unroll
            for (int jj = 0; jj < 2; ++jj) {
                float4* __restrict__ o =
                    (float4*)(out + ((size_t)b * T_DIM + (t0 + j0 + jj)) * C_DIM);
                o[lane] = acc[jj];
            }
        }
    } else {
        // Cold path (2 warps in the whole grid): clamp address, zero weight.
#pragma unroll
        for (int j = 0; j < 4; ++j) {
            float4 acc = make_float4(0.f, 0.f, 0.f, 0.f);
            const float w3[3] = {wm[j], w0[j], wp[j]};
#pragma unroll
            for (int i = -1; i <= 1; ++i) {
                const int s    = r[j] + i;
                float     wgt  = w3[i + 1];
                if (s < 0) wgt = 0.f;
                const int s_ld = (s < 0) ? 0 : s;
                const float4 v = row[s_ld * C4 + lane];
                acc.x = fmaf(wgt, v.x, acc.x);
                acc.y = fmaf(wgt, v.y, acc.y);
                acc.z = fmaf(wgt, v.z, acc.z);
                acc.w = fmaf(wgt, v.w, acc.w);
            }
            float4* __restrict__ o =
                (float4*)(out + ((size_t)b * T_DIM + (t0 + j)) * C_DIM);
            o[lane] = acc;
        }
    }
}

extern "C" void kernel_launch(void* const* d_in, const int* in_sizes, int n_in,
                              void* d_out, int out_size) {
    const float* inp = (const float*)d_in[0];   // (B, S, C) fp32
    const float* sw  = (const float*)d_in[1];   // (B, T)   fp32
    float* out       = (float*)d_out;           // (B, T, C) fp32

    dim3 grid(T_DIM / 32, 16, 1);   // (64, 16) = 1024 blocks
    dim3 block(256, 1, 1);
    shifting_window_kernel<<<grid, block>>>(inp, sw, out);
}